// round 1
// baseline (speedup 1.0000x reference)
#include <cuda_runtime.h>
#include <cuda_bf16.h>
#include <math.h>

// ---------------------------------------------------------------------------
// Problem constants: B=2, S=2048, D=768, H=12, Dk=64, F=3072
// ---------------------------------------------------------------------------
#define BB   2
#define SS_  2048
#define DD   768
#define HH   12
#define DK   64
#define FF   3072
#define MTOT 4096              // B*S
#define BH   24                // B*H
#define QKVD 2304              // 3*D
#define SCORES_PER_BH 4194304  // S*S

typedef __nv_bfloat16 bf16;

// ---------------------------------------------------------------------------
// Device scratch (allocation-free; __device__ globals per harness rules)
// ---------------------------------------------------------------------------
__device__ bf16 gb_wqkv[QKVD * DD];            // 1.77M
__device__ bf16 gb_wo[DD * DD];                // 590K
__device__ bf16 gb_w13[2 * FF * DD];           // 4.72M
__device__ bf16 gb_w2[DD * FF];                // 2.36M
__device__ bf16 gb_xn[MTOT * DD];
__device__ bf16 gb_qkv[MTOT * QKVD];
__device__ bf16 gb_vt[BH * DK * SS_];          // V transposed: [bh][d][s]
__device__ bf16 gb_probs[(size_t)BH * SCORES_PER_BH];  // 201 MB scores/probs
__device__ bf16 gb_attn[MTOT * DD];
__device__ float gb_h[MTOT * DD];
__device__ bf16 gb_hn[MTOT * DD];
__device__ bf16 gb_ug[MTOT * 2 * FF];
__device__ bf16 gb_t[MTOT * FF];
__device__ unsigned gb_maskbits[BB * SS_ * (SS_ / 32)]; // bit-packed mask

// ---------------------------------------------------------------------------
// MMA / ldmatrix helpers
// ---------------------------------------------------------------------------
__device__ __forceinline__ void ldsm_x4(unsigned* r, const void* p) {
    unsigned addr = (unsigned)__cvta_generic_to_shared(p);
    asm volatile("ldmatrix.sync.aligned.m8n8.x4.shared.b16 {%0,%1,%2,%3}, [%4];\n"
                 : "=r"(r[0]), "=r"(r[1]), "=r"(r[2]), "=r"(r[3]) : "r"(addr));
}

__device__ __forceinline__ void mma_bf16(float* c, const unsigned* a, const unsigned* b) {
    asm volatile(
        "mma.sync.aligned.m16n8k16.row.col.f32.bf16.bf16.f32 "
        "{%0,%1,%2,%3}, {%4,%5,%6,%7}, {%8,%9}, {%0,%1,%2,%3};\n"
        : "+f"(c[0]), "+f"(c[1]), "+f"(c[2]), "+f"(c[3])
        : "r"(a[0]), "r"(a[1]), "r"(a[2]), "r"(a[3]), "r"(b[0]), "r"(b[1]));
}

// Swizzled smem index: rows of 32 bf16 (64B), 16B chunks XOR'ed by (row>>1)&3
__device__ __forceinline__ int sw_idx(int row, int k) {
    int chunk = k >> 3;
    int within = k & 7;
    return row * 32 + (((chunk ^ ((row >> 1) & 3)) << 3) | within);
}

// ---------------------------------------------------------------------------
// Generic NT GEMM tile:  C[m,n] = sum_k A[m,k] * B[n,k]   (bf16 x bf16 -> f32)
// Block = 256 threads (8 warps as 4(M) x 2(N)), tile BM x BN, BK=32.
// ---------------------------------------------------------------------------
template <int BM, int BN, typename Epi>
__device__ __forceinline__ void gemm_block(const bf16* __restrict__ A, int lda,
                                           const bf16* __restrict__ B, int ldb,
                                           int K, Epi epi) {
    constexpr int BK = 32;
    __shared__ __align__(16) bf16 As[BM * BK];
    __shared__ __align__(16) bf16 Bs[BN * BK];

    const int tid  = threadIdx.x;
    const int lane = tid & 31;
    const int warp = tid >> 5;
    const int wr   = warp >> 1;   // 0..3  (M direction, 32 rows each)
    const int wc   = warp & 1;    // 0..1  (N direction, BN/2 cols each)
    constexpr int WN = BN / 2;
    constexpr int NA = WN / 8;    // n-atoms per warp

    const int m0 = blockIdx.x * BM;
    const int n0 = blockIdx.y * BN;

    float acc[2][NA][4];
#pragma unroll
    for (int i = 0; i < 2; ++i)
#pragma unroll
        for (int j = 0; j < NA; ++j)
#pragma unroll
            for (int e = 0; e < 4; ++e) acc[i][j][e] = 0.f;

    const int lrow8  = lane & 7;
    const int rowadd = ((lane >> 3) & 1) * 8;
    const int kadd   = ((lane >> 4) & 1) * 8;

    for (int kt = 0; kt < K; kt += BK) {
        // ---- load tiles into swizzled smem (16B per thread-iter) ----
#pragma unroll
        for (int i = 0; i < (BM * BK) / (8 * 256); ++i) {
            int lin = i * 256 + tid;
            int row = lin >> 2;
            int chunk = lin & 3;
            uint4 v = *reinterpret_cast<const uint4*>(
                A + (size_t)(m0 + row) * lda + kt + chunk * 8);
            *reinterpret_cast<uint4*>(&As[sw_idx(row, chunk * 8)]) = v;
        }
#pragma unroll
        for (int i = 0; i < (BN * BK) / (8 * 256); ++i) {
            int lin = i * 256 + tid;
            int row = lin >> 2;
            int chunk = lin & 3;
            uint4 v = *reinterpret_cast<const uint4*>(
                B + (size_t)(n0 + row) * ldb + kt + chunk * 8);
            *reinterpret_cast<uint4*>(&Bs[sw_idx(row, chunk * 8)]) = v;
        }
        __syncthreads();

#pragma unroll
        for (int ks = 0; ks < 2; ++ks) {
            unsigned af[2][4];
#pragma unroll
            for (int im = 0; im < 2; ++im) {
                int r  = wr * 32 + im * 16 + lrow8 + rowadd;
                int kc = ks * 16 + kadd;
                ldsm_x4(af[im], &As[sw_idx(r, kc)]);
            }
            unsigned bfr[NA][2];
#pragma unroll
            for (int p = 0; p < NA / 2; ++p) {
                int r  = wc * WN + p * 16 + lrow8 + rowadd;
                int kc = ks * 16 + kadd;
                unsigned t4[4];
                ldsm_x4(t4, &Bs[sw_idx(r, kc)]);
                bfr[2 * p][0]     = t4[0]; bfr[2 * p][1]     = t4[2];
                bfr[2 * p + 1][0] = t4[1]; bfr[2 * p + 1][1] = t4[3];
            }
#pragma unroll
            for (int im = 0; im < 2; ++im)
#pragma unroll
                for (int in = 0; in < NA; ++in)
                    mma_bf16(acc[im][in], af[im], bfr[in]);
        }
        __syncthreads();
    }

    // ---- epilogue ----
    const int g = lane >> 2, t = lane & 3;
#pragma unroll
    for (int im = 0; im < 2; ++im) {
#pragma unroll
        for (int in = 0; in < NA; ++in) {
            int mb = m0 + wr * 32 + im * 16;
            int nb = n0 + wc * WN + in * 8;
            epi(mb + g,     nb + 2 * t,     acc[im][in][0]);
            epi(mb + g,     nb + 2 * t + 1, acc[im][in][1]);
            epi(mb + g + 8, nb + 2 * t,     acc[im][in][2]);
            epi(mb + g + 8, nb + 2 * t + 1, acc[im][in][3]);
        }
    }
}

// ---------------------------------------------------------------------------
// Epilogues
// ---------------------------------------------------------------------------
struct EpiQKV {
    __device__ void operator()(int m, int n, float v) const {
        gb_qkv[(size_t)m * QKVD + n] = __float2bfloat16(v);
    }
};
struct EpiQK {
    size_t off;
    __device__ void operator()(int m, int n, float v) const {
        gb_probs[off + (size_t)m * SS_ + n] = __float2bfloat16(v);
    }
};
struct EpiPV {
    int b, h;
    __device__ void operator()(int m, int n, float v) const {
        gb_attn[((size_t)(b * SS_ + m)) * DD + h * DK + n] = __float2bfloat16(v);
    }
};
struct EpiWO {
    const float* x;
    __device__ void operator()(int m, int n, float v) const {
        size_t i = (size_t)m * DD + n;
        gb_h[i] = x[i] + v;
    }
};
struct EpiW13 {
    __device__ void operator()(int m, int n, float v) const {
        gb_ug[(size_t)m * (2 * FF) + n] = __float2bfloat16(v);
    }
};
struct EpiW2 {
    float* out;
    __device__ void operator()(int m, int n, float v) const {
        size_t i = (size_t)m * DD + n;
        out[i] = gb_h[i] + v;
    }
};

// ---------------------------------------------------------------------------
// GEMM wrapper kernels
// ---------------------------------------------------------------------------
__global__ void __launch_bounds__(256) gemm_qkv_kernel() {
    gemm_block<128, 128>(gb_xn, DD, gb_wqkv, DD, DD, EpiQKV{});
}
__global__ void __launch_bounds__(256) gemm_qk_kernel() {
    int bh = blockIdx.z;
    int b = bh / HH, h = bh % HH;
    const bf16* A = gb_qkv + (size_t)b * SS_ * QKVD + h * DK;        // Q
    const bf16* Bp = gb_qkv + (size_t)b * SS_ * QKVD + DD + h * DK;  // K
    gemm_block<128, 128>(A, QKVD, Bp, QKVD, DK, EpiQK{(size_t)bh * SCORES_PER_BH});
}
__global__ void __launch_bounds__(256) gemm_pv_kernel() {
    int bh = blockIdx.z;
    int b = bh / HH, h = bh % HH;
    const bf16* A = gb_probs + (size_t)bh * SCORES_PER_BH;
    const bf16* Bp = gb_vt + (size_t)bh * DK * SS_;
    gemm_block<128, 64>(A, SS_, Bp, SS_, SS_, EpiPV{b, h});
}
__global__ void __launch_bounds__(256) gemm_wo_kernel(const float* __restrict__ x) {
    gemm_block<128, 128>(gb_attn, DD, gb_wo, DD, DD, EpiWO{x});
}
__global__ void __launch_bounds__(256) gemm_w13_kernel() {
    gemm_block<128, 128>(gb_hn, DD, gb_w13, DD, DD, EpiW13{});
}
__global__ void __launch_bounds__(256) gemm_w2_kernel(float* __restrict__ out) {
    gemm_block<128, 128>(gb_t, FF, gb_w2, FF, FF, EpiW2{out});
}

// ---------------------------------------------------------------------------
// Elementwise / support kernels
// ---------------------------------------------------------------------------
__global__ void cvt_weights_kernel(const float* __restrict__ wq, const float* __restrict__ wk,
                                   const float* __restrict__ wv, const float* __restrict__ wo,
                                   const float* __restrict__ w1, const float* __restrict__ w2,
                                   const float* __restrict__ w3) {
    const int N1 = DD * DD;      // 589824
    const int N2 = FF * DD;      // 2359296
    const int TOT = 4 * N1 + 3 * N2;
    int idx = blockIdx.x * blockDim.x + threadIdx.x;
    if (idx >= TOT) return;
    if (idx < N1)            gb_wqkv[idx] = __float2bfloat16(wq[idx]);
    else if (idx < 2 * N1)   gb_wqkv[idx] = __float2bfloat16(wk[idx - N1]);
    else if (idx < 3 * N1)   gb_wqkv[idx] = __float2bfloat16(wv[idx - 2 * N1]);
    else if (idx < 4 * N1)   gb_wo[idx - 3 * N1] = __float2bfloat16(wo[idx - 3 * N1]);
    else if (idx < 4 * N1 + N2) {
        int i = idx - 4 * N1;  gb_w13[i] = __float2bfloat16(w1[i]);
    } else if (idx < 4 * N1 + 2 * N2) {
        int i = idx - 4 * N1 - N2;  gb_w13[N2 + i] = __float2bfloat16(w3[i]);
    } else {
        int i = idx - 4 * N1 - 2 * N2;  gb_w2[i] = __float2bfloat16(w2[i]);
    }
}

__device__ __forceinline__ void rmsnorm_row(const float* __restrict__ in,
                                            const float* __restrict__ g,
                                            bf16* __restrict__ out) {
    __shared__ float red[8];
    int tid = threadIdx.x, lane = tid & 31, warp = tid >> 5;
    float ss = 0.f;
#pragma unroll
    for (int c = 0; c < 3; ++c) {
        float a = in[c * 256 + tid];
        ss += a * a;
    }
#pragma unroll
    for (int o = 16; o; o >>= 1) ss += __shfl_xor_sync(0xffffffffu, ss, o);
    if (lane == 0) red[warp] = ss;
    __syncthreads();
    float tot = 0.f;
#pragma unroll
    for (int i = 0; i < 8; ++i) tot += red[i];
    float sc = rsqrtf(tot / (float)DD + 1e-5f);
#pragma unroll
    for (int c = 0; c < 3; ++c) {
        int j = c * 256 + tid;
        out[j] = __float2bfloat16(g[j] * in[j] * sc);
    }
}

__global__ void rmsnorm_x_kernel(const float* __restrict__ x, const float* __restrict__ g) {
    int row = blockIdx.x;
    rmsnorm_row(x + (size_t)row * DD, g, gb_xn + (size_t)row * DD);
}
__global__ void rmsnorm_h_kernel(const float* __restrict__ g) {
    int row = blockIdx.x;
    rmsnorm_row(gb_h + (size_t)row * DD, g, gb_hn + (size_t)row * DD);
}

__global__ void mask_pack_kernel(const int* __restrict__ mask) {
    int row = blockIdx.x;               // b*S + q
    int tid = threadIdx.x, lane = tid & 31, warp = tid >> 5;
    const int* mrow = mask + (size_t)row * SS_;
#pragma unroll
    for (int c = 0; c < 8; ++c) {
        int j = c * 256 + tid;
        unsigned bal = __ballot_sync(0xffffffffu, mrow[j] != 0);
        if (lane == 0) gb_maskbits[(size_t)row * 64 + c * 8 + warp] = bal;
    }
}

__global__ void v_transpose_kernel() {
    int idx = blockIdx.x * blockDim.x + threadIdx.x;
    if (idx >= BH * DK * SS_) return;
    int s = idx & (SS_ - 1);
    int d = (idx >> 11) & (DK - 1);
    int bh = idx >> 17;
    int b = bh / HH, h = bh % HH;
    gb_vt[idx] = gb_qkv[((size_t)(b * SS_ + s)) * QKVD + 2 * DD + h * DK + d];
}

__global__ void softmax_kernel() {
    int row = blockIdx.x;
    int bh = blockIdx.y;
    int b = bh / HH;
    int tid = threadIdx.x, lane = tid & 31, warp = tid >> 5;
    size_t base = (size_t)bh * SCORES_PER_BH + (size_t)row * SS_;
    const unsigned* mb = gb_maskbits + (size_t)(b * SS_ + row) * 64;

    float v[8];
#pragma unroll
    for (int c = 0; c < 8; ++c) {
        int j = c * 256 + tid;
        unsigned w = mb[c * 8 + warp];
        bool on = (w >> (j & 31)) & 1u;
        v[c] = on ? __bfloat162float(gb_probs[base + j]) * 0.125f : -1e9f;
    }
    __shared__ float red[8];
    float m = v[0];
#pragma unroll
    for (int c = 1; c < 8; ++c) m = fmaxf(m, v[c]);
#pragma unroll
    for (int o = 16; o; o >>= 1) m = fmaxf(m, __shfl_xor_sync(0xffffffffu, m, o));
    if (lane == 0) red[warp] = m;
    __syncthreads();
    float rm = red[0];
#pragma unroll
    for (int i = 1; i < 8; ++i) rm = fmaxf(rm, red[i]);
    __syncthreads();

    float esum = 0.f;
#pragma unroll
    for (int c = 0; c < 8; ++c) {
        v[c] = __expf(v[c] - rm);
        esum += v[c];
    }
#pragma unroll
    for (int o = 16; o; o >>= 1) esum += __shfl_xor_sync(0xffffffffu, esum, o);
    if (lane == 0) red[warp] = esum;
    __syncthreads();
    float tot = 0.f;
#pragma unroll
    for (int i = 0; i < 8; ++i) tot += red[i];
    float inv = 1.f / tot;
#pragma unroll
    for (int c = 0; c < 8; ++c) {
        int j = c * 256 + tid;
        gb_probs[base + j] = __float2bfloat16(v[c] * inv);
    }
}

__global__ void silu_gate_kernel() {
    int idx = blockIdx.x * blockDim.x + threadIdx.x;
    if (idx >= MTOT * FF) return;
    int m = idx / FF;
    int j = idx - m * FF;
    float u = __bfloat162float(gb_ug[(size_t)m * (2 * FF) + j]);
    float g = __bfloat162float(gb_ug[(size_t)m * (2 * FF) + FF + j]);
    float s = u / (1.f + __expf(-u));
    gb_t[idx] = __float2bfloat16(s * g);
}

// ---------------------------------------------------------------------------
// Launch
// ---------------------------------------------------------------------------
extern "C" void kernel_launch(void* const* d_in, const int* in_sizes, int n_in,
                              void* d_out, int out_size) {
    const float* x      = (const float*)d_in[0];
    const int*   mask   = (const int*)d_in[1];
    const float* wq     = (const float*)d_in[2];
    const float* wk     = (const float*)d_in[3];
    const float* wv     = (const float*)d_in[4];
    const float* wo     = (const float*)d_in[5];
    const float* w1     = (const float*)d_in[6];
    const float* w2     = (const float*)d_in[7];
    const float* w3     = (const float*)d_in[8];
    const float* gattn  = (const float*)d_in[9];
    const float* gffn   = (const float*)d_in[10];
    float* out          = (float*)d_out;

    const int CVT_TOT = 4 * DD * DD + 3 * FF * DD;
    cvt_weights_kernel<<<(CVT_TOT + 255) / 256, 256>>>(wq, wk, wv, wo, w1, w2, w3);
    mask_pack_kernel<<<BB * SS_, 256>>>(mask);
    rmsnorm_x_kernel<<<MTOT, 256>>>(x, gattn);

    gemm_qkv_kernel<<<dim3(MTOT / 128, QKVD / 128), 256>>>();
    v_transpose_kernel<<<(BH * DK * SS_ + 255) / 256, 256>>>();

    gemm_qk_kernel<<<dim3(SS_ / 128, SS_ / 128, BH), 256>>>();
    softmax_kernel<<<dim3(SS_, BH), 256>>>();
    gemm_pv_kernel<<<dim3(SS_ / 128, 1, BH), 256>>>();

    gemm_wo_kernel<<<dim3(MTOT / 128, DD / 128), 256>>>(x);
    rmsnorm_h_kernel<<<MTOT, 256>>>(gffn);

    gemm_w13_kernel<<<dim3(MTOT / 128, (2 * FF) / 128), 256>>>();
    silu_gate_kernel<<<(MTOT * FF + 255) / 256, 256>>>();
    gemm_w2_kernel<<<dim3(MTOT / 128, DD / 128), 256>>>(out);
}

// round 2
// speedup vs baseline: 1.5136x; 1.5136x over previous
#include <cuda_runtime.h>
#include <cuda_bf16.h>
#include <math.h>

// ---------------------------------------------------------------------------
// Problem constants: B=2, S=2048, D=768, H=12, Dk=64, F=3072
// ---------------------------------------------------------------------------
#define BB   2
#define SS_  2048
#define DD   768
#define HH   12
#define DK   64
#define FF   3072
#define MTOT 4096              // B*S
#define BH   24                // B*H
#define QKVD 2304              // 3*D

typedef __nv_bfloat16 bf16;

// ---------------------------------------------------------------------------
// Device scratch (allocation-free; __device__ globals per harness rules)
// ---------------------------------------------------------------------------
__device__ bf16 gb_wqkv[QKVD * DD];
__device__ bf16 gb_wo[DD * DD];
__device__ bf16 gb_w13[2 * FF * DD];
__device__ bf16 gb_w2[DD * FF];
__device__ bf16 gb_xn[MTOT * DD];
__device__ bf16 gb_qkv[MTOT * QKVD];
__device__ bf16 gb_attn[MTOT * DD];
__device__ float gb_h[MTOT * DD];
__device__ bf16 gb_hn[MTOT * DD];
__device__ bf16 gb_ug[MTOT * 2 * FF];
__device__ bf16 gb_t[MTOT * FF];
__device__ unsigned gb_maskbits[BB * SS_ * (SS_ / 32)]; // bit-packed mask

// ---------------------------------------------------------------------------
// MMA / ldmatrix / cp.async helpers
// ---------------------------------------------------------------------------
__device__ __forceinline__ void ldsm_x4(unsigned* r, const void* p) {
    unsigned addr = (unsigned)__cvta_generic_to_shared(p);
    asm volatile("ldmatrix.sync.aligned.m8n8.x4.shared.b16 {%0,%1,%2,%3}, [%4];\n"
                 : "=r"(r[0]), "=r"(r[1]), "=r"(r[2]), "=r"(r[3]) : "r"(addr));
}
__device__ __forceinline__ void ldsm_x4_t(unsigned* r, const void* p) {
    unsigned addr = (unsigned)__cvta_generic_to_shared(p);
    asm volatile("ldmatrix.sync.aligned.m8n8.x4.trans.shared.b16 {%0,%1,%2,%3}, [%4];\n"
                 : "=r"(r[0]), "=r"(r[1]), "=r"(r[2]), "=r"(r[3]) : "r"(addr));
}
__device__ __forceinline__ void mma_bf16(float* c, const unsigned* a, const unsigned* b) {
    asm volatile(
        "mma.sync.aligned.m16n8k16.row.col.f32.bf16.bf16.f32 "
        "{%0,%1,%2,%3}, {%4,%5,%6,%7}, {%8,%9}, {%0,%1,%2,%3};\n"
        : "+f"(c[0]), "+f"(c[1]), "+f"(c[2]), "+f"(c[3])
        : "r"(a[0]), "r"(a[1]), "r"(a[2]), "r"(a[3]), "r"(b[0]), "r"(b[1]));
}
__device__ __forceinline__ void cp_async16(void* smem, const void* g) {
    unsigned addr = (unsigned)__cvta_generic_to_shared(smem);
    asm volatile("cp.async.cg.shared.global [%0], [%1], 16;\n" :: "r"(addr), "l"(g));
}
__device__ __forceinline__ void cp_commit() { asm volatile("cp.async.commit_group;\n"); }
template <int N>
__device__ __forceinline__ void cp_wait() { asm volatile("cp.async.wait_group %0;\n" :: "n"(N)); }

__device__ __forceinline__ unsigned pack_bf16x2(float lo, float hi) {
    __nv_bfloat162 h2 = __floats2bfloat162_rn(lo, hi);
    return *reinterpret_cast<unsigned*>(&h2);
}

// Swizzled smem index for 32-halves-wide rows (GEMM tiles)
__device__ __forceinline__ int sw_idx(int row, int k) {
    int chunk = k >> 3, within = k & 7;
    return row * 32 + (((chunk ^ ((row >> 1) & 3)) << 3) | within);
}
// Swizzled smem index for 64-halves-wide rows (flash tiles): conflict-free ldmatrix
__device__ __forceinline__ int sw64(int row, int k) {
    int chunk = k >> 3, within = k & 7;
    return row * 64 + (((chunk ^ (row & 7)) << 3) | within);
}

// ---------------------------------------------------------------------------
// Generic NT GEMM: C[m,n] = sum_k A[m,k]*B[n,k], bf16 in / f32 acc.
// 256 threads (8 warps, 4x2), tile BM x BN, BK=32, cp.async double-buffered.
// ---------------------------------------------------------------------------
template <int BM, int BN, typename Epi>
__device__ __forceinline__ void gemm_block(const bf16* __restrict__ A, int lda,
                                           const bf16* __restrict__ B, int ldb,
                                           int K, Epi epi) {
    constexpr int BK = 32;
    __shared__ __align__(16) bf16 As[2][BM * BK];
    __shared__ __align__(16) bf16 Bs[2][BN * BK];

    const int tid  = threadIdx.x;
    const int lane = tid & 31;
    const int warp = tid >> 5;
    const int wr   = warp >> 1;
    const int wc   = warp & 1;
    constexpr int WN = BN / 2;
    constexpr int NA = WN / 8;

    const int m0 = blockIdx.x * BM;
    const int n0 = blockIdx.y * BN;

    float acc[2][NA][4];
#pragma unroll
    for (int i = 0; i < 2; ++i)
#pragma unroll
        for (int j = 0; j < NA; ++j)
#pragma unroll
            for (int e = 0; e < 4; ++e) acc[i][j][e] = 0.f;

    const int lrow8  = lane & 7;
    const int rowadd = ((lane >> 3) & 1) * 8;
    const int kadd   = ((lane >> 4) & 1) * 8;

    auto load_tiles = [&](int kt, int buf) {
#pragma unroll
        for (int i = 0; i < (BM * BK) / (8 * 256); ++i) {
            int lin = i * 256 + tid;
            int row = lin >> 2, chunk = lin & 3;
            cp_async16(&As[buf][sw_idx(row, chunk * 8)],
                       A + (size_t)(m0 + row) * lda + kt + chunk * 8);
        }
#pragma unroll
        for (int i = 0; i < (BN * BK) / (8 * 256); ++i) {
            int lin = i * 256 + tid;
            int row = lin >> 2, chunk = lin & 3;
            cp_async16(&Bs[buf][sw_idx(row, chunk * 8)],
                       B + (size_t)(n0 + row) * ldb + kt + chunk * 8);
        }
    };

    const int nt = K / BK;
    load_tiles(0, 0);
    cp_commit();

    for (int kt = 0; kt < nt; ++kt) {
        if (kt + 1 < nt) {
            load_tiles((kt + 1) * BK, (kt + 1) & 1);
            cp_commit();
            cp_wait<1>();
        } else {
            cp_wait<0>();
        }
        __syncthreads();

        const bf16* Asb = As[kt & 1];
        const bf16* Bsb = Bs[kt & 1];
#pragma unroll
        for (int ks = 0; ks < 2; ++ks) {
            unsigned af[2][4];
#pragma unroll
            for (int im = 0; im < 2; ++im) {
                int r  = wr * 32 + im * 16 + lrow8 + rowadd;
                int kc = ks * 16 + kadd;
                ldsm_x4(af[im], &Asb[sw_idx(r, kc)]);
            }
            unsigned bfr[NA][2];
#pragma unroll
            for (int p = 0; p < NA / 2; ++p) {
                int r  = wc * WN + p * 16 + lrow8 + rowadd;
                int kc = ks * 16 + kadd;
                unsigned t4[4];
                ldsm_x4(t4, &Bsb[sw_idx(r, kc)]);
                bfr[2 * p][0]     = t4[0]; bfr[2 * p][1]     = t4[2];
                bfr[2 * p + 1][0] = t4[1]; bfr[2 * p + 1][1] = t4[3];
            }
#pragma unroll
            for (int im = 0; im < 2; ++im)
#pragma unroll
                for (int in = 0; in < NA; ++in)
                    mma_bf16(acc[im][in], af[im], bfr[in]);
        }
        __syncthreads();
    }

    const int g = lane >> 2, t = lane & 3;
#pragma unroll
    for (int im = 0; im < 2; ++im) {
#pragma unroll
        for (int in = 0; in < NA; ++in) {
            int mb = m0 + wr * 32 + im * 16;
            int nb = n0 + wc * WN + in * 8;
            epi(mb + g,     nb + 2 * t,     acc[im][in][0]);
            epi(mb + g,     nb + 2 * t + 1, acc[im][in][1]);
            epi(mb + g + 8, nb + 2 * t,     acc[im][in][2]);
            epi(mb + g + 8, nb + 2 * t + 1, acc[im][in][3]);
        }
    }
}

// ---------------------------------------------------------------------------
// Epilogues
// ---------------------------------------------------------------------------
struct EpiQKV {
    __device__ void operator()(int m, int n, float v) const {
        gb_qkv[(size_t)m * QKVD + n] = __float2bfloat16(v);
    }
};
struct EpiWO {
    const float* x;
    __device__ void operator()(int m, int n, float v) const {
        size_t i = (size_t)m * DD + n;
        gb_h[i] = x[i] + v;
    }
};
struct EpiW13 {
    __device__ void operator()(int m, int n, float v) const {
        gb_ug[(size_t)m * (2 * FF) + n] = __float2bfloat16(v);
    }
};
struct EpiW2 {
    float* out;
    __device__ void operator()(int m, int n, float v) const {
        size_t i = (size_t)m * DD + n;
        out[i] = gb_h[i] + v;
    }
};

__global__ void __launch_bounds__(256) gemm_qkv_kernel() {
    gemm_block<128, 128>(gb_xn, DD, gb_wqkv, DD, DD, EpiQKV{});
}
__global__ void __launch_bounds__(256) gemm_wo_kernel(const float* __restrict__ x) {
    gemm_block<128, 128>(gb_attn, DD, gb_wo, DD, DD, EpiWO{x});
}
__global__ void __launch_bounds__(256) gemm_w13_kernel() {
    gemm_block<128, 128>(gb_hn, DD, gb_w13, DD, DD, EpiW13{});
}
__global__ void __launch_bounds__(256) gemm_w2_kernel(float* __restrict__ out) {
    gemm_block<128, 128>(gb_t, FF, gb_w2, FF, FF, EpiW2{out});
}

// ---------------------------------------------------------------------------
// Fused flash attention: per block 128 q-rows of one (b,h); loops 16 kv tiles.
// 8 warps x 16 q-rows. Q frags register-resident. Online softmax, fp32 acc.
// ---------------------------------------------------------------------------
__global__ void __launch_bounds__(256) flash_attn_kernel() {
    __shared__ __align__(16) bf16 smem_all[3 * 128 * 64];   // 48 KB
    bf16* Qs = smem_all;                 // overlaid by mask after Q consumed
    bf16* Ks = smem_all + 128 * 64;
    bf16* Vs = smem_all + 2 * 128 * 64;
    unsigned* Ms = reinterpret_cast<unsigned*>(smem_all);   // [128][4] words

    const int tid  = threadIdx.x;
    const int lane = tid & 31;
    const int w    = tid >> 5;
    const int q0   = blockIdx.x * 128;
    const int bh   = blockIdx.y;
    const int b    = bh / HH, h = bh % HH;

    const int lrow8  = lane & 7;
    const int rowadd = ((lane >> 3) & 1) * 8;
    const int kadd   = ((lane >> 4) & 1) * 8;
    const int g = lane >> 2, t = lane & 3;

    // ---- load Q tile (128x64) and extract A-fragments ----
#pragma unroll
    for (int i = 0; i < 4; ++i) {
        int lin = i * 256 + tid;
        int row = lin >> 3, ch = lin & 7;
        cp_async16(&Qs[sw64(row, ch * 8)],
                   gb_qkv + (size_t)(b * SS_ + q0 + row) * QKVD + h * DK + ch * 8);
    }
    cp_commit();
    cp_wait<0>();
    __syncthreads();

    unsigned aq[4][4];
#pragma unroll
    for (int kb = 0; kb < 4; ++kb)
        ldsm_x4(aq[kb], &Qs[sw64(w * 16 + lrow8 + rowadd, kb * 16 + kadd)]);
    __syncthreads();   // all warps done with Qs before mask overlay

    float oacc[8][4];
#pragma unroll
    for (int j = 0; j < 8; ++j)
#pragma unroll
        for (int e = 0; e < 4; ++e) oacc[j][e] = 0.f;
    float m0r = -3.0e38f, m1r = -3.0e38f, l0 = 0.f, l1 = 0.f;

    for (int kt = 0; kt < 16; ++kt) {
        const int kv0 = kt * 128;
        // ---- stage K, V, mask ----
#pragma unroll
        for (int i = 0; i < 4; ++i) {
            int lin = i * 256 + tid;
            int row = lin >> 3, ch = lin & 7;
            size_t src = (size_t)(b * SS_ + kv0 + row) * QKVD + h * DK + ch * 8;
            cp_async16(&Ks[sw64(row, ch * 8)], gb_qkv + src + DD);
            cp_async16(&Vs[sw64(row, ch * 8)], gb_qkv + src + 2 * DD);
        }
        if (tid < 128)
            cp_async16(&Ms[tid * 4],
                       gb_maskbits + (size_t)(b * SS_ + q0 + tid) * 64 + kt * 4);
        cp_commit();
        cp_wait<0>();
        __syncthreads();

        // ---- scores: S = Q K^T (16x128 per warp) ----
        float sacc[16][4];
#pragma unroll
        for (int j = 0; j < 16; ++j)
#pragma unroll
            for (int e = 0; e < 4; ++e) sacc[j][e] = 0.f;
#pragma unroll
        for (int kb = 0; kb < 4; ++kb) {
#pragma unroll
            for (int pr = 0; pr < 8; ++pr) {
                unsigned t4[4];
                ldsm_x4(t4, &Ks[sw64(pr * 16 + lrow8 + rowadd, kb * 16 + kadd)]);
                unsigned b0[2] = {t4[0], t4[2]}, b1[2] = {t4[1], t4[3]};
                mma_bf16(sacc[2 * pr],     aq[kb], b0);
                mma_bf16(sacc[2 * pr + 1], aq[kb], b1);
            }
        }

        // ---- mask + scale + row max ----
        const int r0 = w * 16 + g;
        float nm0 = -3.0e38f, nm1 = -3.0e38f;
#pragma unroll
        for (int j = 0; j < 16; ++j) {
            unsigned w0 = Ms[r0 * 4 + (j >> 2)];
            unsigned w1 = Ms[(r0 + 8) * 4 + (j >> 2)];
            int c = 8 * j + 2 * t;
            sacc[j][0] = ((w0 >> (c & 31)) & 1u)       ? sacc[j][0] * 0.125f : -1e9f;
            sacc[j][1] = ((w0 >> ((c + 1) & 31)) & 1u) ? sacc[j][1] * 0.125f : -1e9f;
            sacc[j][2] = ((w1 >> (c & 31)) & 1u)       ? sacc[j][2] * 0.125f : -1e9f;
            sacc[j][3] = ((w1 >> ((c + 1) & 31)) & 1u) ? sacc[j][3] * 0.125f : -1e9f;
            nm0 = fmaxf(nm0, fmaxf(sacc[j][0], sacc[j][1]));
            nm1 = fmaxf(nm1, fmaxf(sacc[j][2], sacc[j][3]));
        }
#pragma unroll
        for (int o = 1; o <= 2; o <<= 1) {
            nm0 = fmaxf(nm0, __shfl_xor_sync(0xffffffffu, nm0, o));
            nm1 = fmaxf(nm1, __shfl_xor_sync(0xffffffffu, nm1, o));
        }

        // ---- online softmax rescale ----
        float mn0 = fmaxf(m0r, nm0), mn1 = fmaxf(m1r, nm1);
        float a0 = __expf(m0r - mn0), a1 = __expf(m1r - mn1);
        m0r = mn0; m1r = mn1;
        float rs0 = 0.f, rs1 = 0.f;
#pragma unroll
        for (int j = 0; j < 16; ++j) {
            sacc[j][0] = __expf(sacc[j][0] - mn0);
            sacc[j][1] = __expf(sacc[j][1] - mn0);
            sacc[j][2] = __expf(sacc[j][2] - mn1);
            sacc[j][3] = __expf(sacc[j][3] - mn1);
            rs0 += sacc[j][0] + sacc[j][1];
            rs1 += sacc[j][2] + sacc[j][3];
        }
#pragma unroll
        for (int o = 1; o <= 2; o <<= 1) {
            rs0 += __shfl_xor_sync(0xffffffffu, rs0, o);
            rs1 += __shfl_xor_sync(0xffffffffu, rs1, o);
        }
        l0 = a0 * l0 + rs0;
        l1 = a1 * l1 + rs1;
#pragma unroll
        for (int j = 0; j < 8; ++j) {
            oacc[j][0] *= a0; oacc[j][1] *= a0;
            oacc[j][2] *= a1; oacc[j][3] *= a1;
        }

        // ---- O += P V ----
#pragma unroll
        for (int kb = 0; kb < 8; ++kb) {
            unsigned ap[4];
            ap[0] = pack_bf16x2(sacc[2 * kb][0],     sacc[2 * kb][1]);
            ap[1] = pack_bf16x2(sacc[2 * kb][2],     sacc[2 * kb][3]);
            ap[2] = pack_bf16x2(sacc[2 * kb + 1][0], sacc[2 * kb + 1][1]);
            ap[3] = pack_bf16x2(sacc[2 * kb + 1][2], sacc[2 * kb + 1][3]);
#pragma unroll
            for (int pr = 0; pr < 4; ++pr) {
                unsigned t4[4];
                ldsm_x4_t(t4, &Vs[sw64(kb * 16 + lrow8 + rowadd, pr * 16 + kadd)]);
                unsigned b0[2] = {t4[0], t4[1]}, b1[2] = {t4[2], t4[3]};
                mma_bf16(oacc[2 * pr],     ap, b0);
                mma_bf16(oacc[2 * pr + 1], ap, b1);
            }
        }
        __syncthreads();
    }

    // ---- normalize + write ----
    float inv0 = 1.f / l0, inv1 = 1.f / l1;
    const int qa = b * SS_ + q0 + w * 16 + g;
#pragma unroll
    for (int j = 0; j < 8; ++j) {
        int d0 = h * DK + j * 8 + 2 * t;
        gb_attn[(size_t)qa * DD + d0]           = __float2bfloat16(oacc[j][0] * inv0);
        gb_attn[(size_t)qa * DD + d0 + 1]       = __float2bfloat16(oacc[j][1] * inv0);
        gb_attn[(size_t)(qa + 8) * DD + d0]     = __float2bfloat16(oacc[j][2] * inv1);
        gb_attn[(size_t)(qa + 8) * DD + d0 + 1] = __float2bfloat16(oacc[j][3] * inv1);
    }
}

// ---------------------------------------------------------------------------
// Elementwise / support kernels
// ---------------------------------------------------------------------------
__global__ void cvt_weights_kernel(const float* __restrict__ wq, const float* __restrict__ wk,
                                   const float* __restrict__ wv, const float* __restrict__ wo,
                                   const float* __restrict__ w1, const float* __restrict__ w2,
                                   const float* __restrict__ w3) {
    const int N1 = DD * DD;
    const int N2 = FF * DD;
    const int TOT = 4 * N1 + 3 * N2;
    int idx = blockIdx.x * blockDim.x + threadIdx.x;
    if (idx >= TOT) return;
    if (idx < N1)            gb_wqkv[idx] = __float2bfloat16(wq[idx]);
    else if (idx < 2 * N1)   gb_wqkv[idx] = __float2bfloat16(wk[idx - N1]);
    else if (idx < 3 * N1)   gb_wqkv[idx] = __float2bfloat16(wv[idx - 2 * N1]);
    else if (idx < 4 * N1)   gb_wo[idx - 3 * N1] = __float2bfloat16(wo[idx - 3 * N1]);
    else if (idx < 4 * N1 + N2) {
        int i = idx - 4 * N1;  gb_w13[i] = __float2bfloat16(w1[i]);
    } else if (idx < 4 * N1 + 2 * N2) {
        int i = idx - 4 * N1 - N2;  gb_w13[N2 + i] = __float2bfloat16(w3[i]);
    } else {
        int i = idx - 4 * N1 - 2 * N2;  gb_w2[i] = __float2bfloat16(w2[i]);
    }
}

__device__ __forceinline__ void rmsnorm_row(const float* __restrict__ in,
                                            const float* __restrict__ g,
                                            bf16* __restrict__ out) {
    __shared__ float red[8];
    int tid = threadIdx.x, lane = tid & 31, warp = tid >> 5;
    float ss = 0.f;
#pragma unroll
    for (int c = 0; c < 3; ++c) {
        float a = in[c * 256 + tid];
        ss += a * a;
    }
#pragma unroll
    for (int o = 16; o; o >>= 1) ss += __shfl_xor_sync(0xffffffffu, ss, o);
    if (lane == 0) red[warp] = ss;
    __syncthreads();
    float tot = 0.f;
#pragma unroll
    for (int i = 0; i < 8; ++i) tot += red[i];
    float sc = rsqrtf(tot / (float)DD + 1e-5f);
#pragma unroll
    for (int c = 0; c < 3; ++c) {
        int j = c * 256 + tid;
        out[j] = __float2bfloat16(g[j] * in[j] * sc);
    }
}

__global__ void rmsnorm_x_kernel(const float* __restrict__ x, const float* __restrict__ g) {
    rmsnorm_row(x + (size_t)blockIdx.x * DD, g, gb_xn + (size_t)blockIdx.x * DD);
}
__global__ void rmsnorm_h_kernel(const float* __restrict__ g) {
    rmsnorm_row(gb_h + (size_t)blockIdx.x * DD, g, gb_hn + (size_t)blockIdx.x * DD);
}

__global__ void mask_pack_kernel(const int* __restrict__ mask) {
    int row = blockIdx.x;
    int tid = threadIdx.x, lane = tid & 31, warp = tid >> 5;
    const int* mrow = mask + (size_t)row * SS_;
#pragma unroll
    for (int c = 0; c < 8; ++c) {
        int j = c * 256 + tid;
        unsigned bal = __ballot_sync(0xffffffffu, mrow[j] != 0);
        if (lane == 0) gb_maskbits[(size_t)row * 64 + c * 8 + warp] = bal;
    }
}

__global__ void silu_gate_kernel() {
    int idx = blockIdx.x * blockDim.x + threadIdx.x;
    if (idx >= MTOT * FF) return;
    int m = idx / FF;
    int j = idx - m * FF;
    float u = __bfloat162float(gb_ug[(size_t)m * (2 * FF) + j]);
    float gt = __bfloat162float(gb_ug[(size_t)m * (2 * FF) + FF + j]);
    float s = u / (1.f + __expf(-u));
    gb_t[idx] = __float2bfloat16(s * gt);
}

// ---------------------------------------------------------------------------
// Launch
// ---------------------------------------------------------------------------
extern "C" void kernel_launch(void* const* d_in, const int* in_sizes, int n_in,
                              void* d_out, int out_size) {
    const float* x      = (const float*)d_in[0];
    const int*   mask   = (const int*)d_in[1];
    const float* wq     = (const float*)d_in[2];
    const float* wk     = (const float*)d_in[3];
    const float* wv     = (const float*)d_in[4];
    const float* wo     = (const float*)d_in[5];
    const float* w1     = (const float*)d_in[6];
    const float* w2     = (const float*)d_in[7];
    const float* w3     = (const float*)d_in[8];
    const float* gattn  = (const float*)d_in[9];
    const float* gffn   = (const float*)d_in[10];
    float* out          = (float*)d_out;

    const int CVT_TOT = 4 * DD * DD + 3 * FF * DD;
    cvt_weights_kernel<<<(CVT_TOT + 255) / 256, 256>>>(wq, wk, wv, wo, w1, w2, w3);
    mask_pack_kernel<<<BB * SS_, 256>>>(mask);
    rmsnorm_x_kernel<<<MTOT, 256>>>(x, gattn);

    gemm_qkv_kernel<<<dim3(MTOT / 128, QKVD / 128), 256>>>();
    flash_attn_kernel<<<dim3(SS_ / 128, BH), 256>>>();

    gemm_wo_kernel<<<dim3(MTOT / 128, DD / 128), 256>>>(x);
    rmsnorm_h_kernel<<<MTOT, 256>>>(gffn);

    gemm_w13_kernel<<<dim3(MTOT / 128, (2 * FF) / 128), 256>>>();
    silu_gate_kernel<<<(MTOT * FF + 255) / 256, 256>>>();
    gemm_w2_kernel<<<dim3(MTOT / 128, DD / 128), 256>>>(out);
}

// round 4
// speedup vs baseline: 1.6492x; 1.0896x over previous
#include <cuda_runtime.h>
#include <cuda_bf16.h>
#include <math.h>
#include <stdint.h>

// ---------------------------------------------------------------------------
// Problem constants: B=2, S=2048, D=768, H=12, Dk=64, F=3072
// ---------------------------------------------------------------------------
#define BB   2
#define SS_  2048
#define DD   768
#define HH   12
#define DK   64
#define FF   3072
#define MTOT 4096              // B*S
#define BH   24                // B*H
#define QKVD 2304              // 3*D

typedef __nv_bfloat16 bf16;

// ---------------------------------------------------------------------------
// Device scratch (allocation-free; __device__ globals per harness rules)
// ---------------------------------------------------------------------------
__device__ bf16 gb_wqkv[QKVD * DD];
__device__ bf16 gb_wo[DD * DD];
__device__ bf16 gb_w13[2 * FF * DD];
__device__ bf16 gb_w2[DD * FF];
__device__ bf16 gb_xn[MTOT * DD];
__device__ bf16 gb_qkv[MTOT * QKVD];
__device__ bf16 gb_attn[MTOT * DD];
__device__ float gb_h[MTOT * DD];
__device__ bf16 gb_hn[MTOT * DD];
__device__ bf16 gb_ug[MTOT * 2 * FF];
__device__ bf16 gb_t[MTOT * FF];
__device__ unsigned gb_maskbits[BB * SS_ * (SS_ / 32)];

// ---------------------------------------------------------------------------
// MMA / ldmatrix / cp.async helpers
// ---------------------------------------------------------------------------
__device__ __forceinline__ void ldsm_x4(unsigned* r, const void* p) {
    unsigned addr = (unsigned)__cvta_generic_to_shared(p);
    asm volatile("ldmatrix.sync.aligned.m8n8.x4.shared.b16 {%0,%1,%2,%3}, [%4];\n"
                 : "=r"(r[0]), "=r"(r[1]), "=r"(r[2]), "=r"(r[3]) : "r"(addr));
}
__device__ __forceinline__ void ldsm_x4_t(unsigned* r, const void* p) {
    unsigned addr = (unsigned)__cvta_generic_to_shared(p);
    asm volatile("ldmatrix.sync.aligned.m8n8.x4.trans.shared.b16 {%0,%1,%2,%3}, [%4];\n"
                 : "=r"(r[0]), "=r"(r[1]), "=r"(r[2]), "=r"(r[3]) : "r"(addr));
}
__device__ __forceinline__ void mma_bf16(float* c, const unsigned* a, const unsigned* b) {
    asm volatile(
        "mma.sync.aligned.m16n8k16.row.col.f32.bf16.bf16.f32 "
        "{%0,%1,%2,%3}, {%4,%5,%6,%7}, {%8,%9}, {%0,%1,%2,%3};\n"
        : "+f"(c[0]), "+f"(c[1]), "+f"(c[2]), "+f"(c[3])
        : "r"(a[0]), "r"(a[1]), "r"(a[2]), "r"(a[3]), "r"(b[0]), "r"(b[1]));
}
__device__ __forceinline__ void cp_async16(void* smem, const void* g) {
    unsigned addr = (unsigned)__cvta_generic_to_shared(smem);
    asm volatile("cp.async.cg.shared.global [%0], [%1], 16;\n" :: "r"(addr), "l"(g));
}
__device__ __forceinline__ void cp_commit() { asm volatile("cp.async.commit_group;\n"); }
template <int N>
__device__ __forceinline__ void cp_wait() { asm volatile("cp.async.wait_group %0;\n" :: "n"(N)); }

__device__ __forceinline__ unsigned pack_bf16x2(float lo, float hi) {
    __nv_bfloat162 h2 = __floats2bfloat162_rn(lo, hi);
    return *reinterpret_cast<unsigned*>(&h2);
}

// Swizzled index within a 128B-row tile (row-major, 64 halves per row).
// Returns HALF index. Conflict-free for ldmatrix + cp.async.
__device__ __forceinline__ int sw64(int row, int k) {
    int chunk = k >> 3, within = k & 7;
    return row * 64 + (((chunk ^ (row & 7)) << 3) | within);
}

// ---------------------------------------------------------------------------
// Classic NT GEMM (mma.sync): C[m,n] = sum_k A[m,k]*B[n,k].
// BM=BN=128, BK=64. 256 threads = 8 warps (4 M x 2 N), warp tile 32x64.
// 3-stage cp.async ring, ONE barrier per k-tile.
//   iter kt: wait(stage kt) -> barrier -> issue loads(stage kt+2) -> compute kt
// Safety: loads at kt target (kt+2)%3; any laggard is in compute kt-1 using
// (kt-1)%3 == (kt+2)%3 -- but loads are issued only AFTER the barrier, which
// guarantees all threads finished compute kt-1.
// ---------------------------------------------------------------------------
#define G_BK 64
#define G_STAGE_BYTES (2 * 128 * G_BK * 2)   // A 16KB + B 16KB = 32KB
#define G_NSTAGE 3
#define G_SMEM (G_NSTAGE * G_STAGE_BYTES)    // 96KB

template <typename Epi>
__device__ __forceinline__ void gemm_block(const bf16* __restrict__ A, int lda,
                                           const bf16* __restrict__ B, int ldb,
                                           int K, Epi epi) {
    extern __shared__ __align__(16) char dyn[];

    const int tid  = threadIdx.x;
    const int lane = tid & 31;
    const int warp = tid >> 5;
    const int wr   = warp >> 1;   // 0..3
    const int wc   = warp & 1;    // 0..1

    const int m0 = blockIdx.x * 128;
    const int n0 = blockIdx.y * 128;

    float acc[2][8][4];
#pragma unroll
    for (int i = 0; i < 2; ++i)
#pragma unroll
        for (int j = 0; j < 8; ++j)
#pragma unroll
            for (int e = 0; e < 4; ++e) acc[i][j][e] = 0.f;

    const int lrow8  = lane & 7;
    const int rowadd = ((lane >> 3) & 1) * 8;
    const int kadd   = ((lane >> 4) & 1) * 8;

    auto load_tile = [&](int kt, int s) {
        bf16* As = (bf16*)(dyn + s * G_STAGE_BYTES);
        bf16* Bs = As + 128 * 64;
#pragma unroll
        for (int i = 0; i < 4; ++i) {   // A: 128 rows x 8 chunks
            int lin = i * 256 + tid;
            int row = lin >> 3, ch = lin & 7;
            cp_async16(&As[sw64(row, ch * 8)],
                       A + (size_t)(m0 + row) * lda + kt * G_BK + ch * 8);
        }
#pragma unroll
        for (int i = 0; i < 4; ++i) {   // B: 128 rows x 8 chunks
            int lin = i * 256 + tid;
            int row = lin >> 3, ch = lin & 7;
            cp_async16(&Bs[sw64(row, ch * 8)],
                       B + (size_t)(n0 + row) * ldb + kt * G_BK + ch * 8);
        }
    };

    const int nt = K / G_BK;
    load_tile(0, 0);
    cp_commit();
    load_tile(1, 1);
    cp_commit();

    for (int kt = 0; kt < nt; ++kt) {
        if (kt + 1 < nt) cp_wait<1>(); else cp_wait<0>();
        __syncthreads();
        if (kt + 2 < nt) {
            load_tile(kt + 2, (kt + 2) % 3);
            cp_commit();
        }

        const bf16* As = (const bf16*)(dyn + (kt % 3) * G_STAGE_BYTES);
        const bf16* Bs = As + 128 * 64;
#pragma unroll
        for (int ks = 0; ks < 4; ++ks) {
            unsigned af[2][4];
#pragma unroll
            for (int im = 0; im < 2; ++im)
                ldsm_x4(af[im], &As[sw64(wr * 32 + im * 16 + lrow8 + rowadd,
                                         ks * 16 + kadd)]);
            unsigned bfr[8][2];
#pragma unroll
            for (int p = 0; p < 4; ++p) {
                unsigned t4[4];
                ldsm_x4(t4, &Bs[sw64(wc * 64 + p * 16 + lrow8 + rowadd,
                                     ks * 16 + kadd)]);
                bfr[2 * p][0]     = t4[0]; bfr[2 * p][1]     = t4[2];
                bfr[2 * p + 1][0] = t4[1]; bfr[2 * p + 1][1] = t4[3];
            }
#pragma unroll
            for (int im = 0; im < 2; ++im)
#pragma unroll
                for (int in = 0; in < 8; ++in)
                    mma_bf16(acc[im][in], af[im], bfr[in]);
        }
    }

    const int g = lane >> 2, t = lane & 3;
#pragma unroll
    for (int im = 0; im < 2; ++im) {
#pragma unroll
        for (int in = 0; in < 8; ++in) {
            int mb = m0 + wr * 32 + im * 16;
            int nb = n0 + wc * 64 + in * 8;
            epi(mb + g,     nb + 2 * t,     acc[im][in][0]);
            epi(mb + g,     nb + 2 * t + 1, acc[im][in][1]);
            epi(mb + g + 8, nb + 2 * t,     acc[im][in][2]);
            epi(mb + g + 8, nb + 2 * t + 1, acc[im][in][3]);
        }
    }
}

// ---------------------------------------------------------------------------
// Epilogues
// ---------------------------------------------------------------------------
struct EpiQKV {
    __device__ void operator()(int m, int n, float v) const {
        gb_qkv[(size_t)m * QKVD + n] = __float2bfloat16(v);
    }
};
struct EpiWO {
    const float* x;
    __device__ void operator()(int m, int n, float v) const {
        size_t i = (size_t)m * DD + n;
        gb_h[i] = x[i] + v;
    }
};
struct EpiW13 {
    __device__ void operator()(int m, int n, float v) const {
        gb_ug[(size_t)m * (2 * FF) + n] = __float2bfloat16(v);
    }
};
struct EpiW2 {
    float* out;
    __device__ void operator()(int m, int n, float v) const {
        size_t i = (size_t)m * DD + n;
        out[i] = gb_h[i] + v;
    }
};

__global__ void __launch_bounds__(256) gemm_qkv_kernel() {
    gemm_block(gb_xn, DD, gb_wqkv, DD, DD, EpiQKV{});
}
__global__ void __launch_bounds__(256) gemm_wo_kernel(const float* __restrict__ x) {
    gemm_block(gb_attn, DD, gb_wo, DD, DD, EpiWO{x});
}
__global__ void __launch_bounds__(256) gemm_w13_kernel() {
    gemm_block(gb_hn, DD, gb_w13, DD, DD, EpiW13{});
}
__global__ void __launch_bounds__(256) gemm_w2_kernel(float* __restrict__ out) {
    gemm_block(gb_t, FF, gb_w2, FF, FF, EpiW2{out});
}

// ---------------------------------------------------------------------------
// Flash attention with 3-stage K/V/mask prefetch ring, one barrier per tile.
// Dynamic smem: [0,16KB) Q (later: 3 x 2KB mask buffers), [16KB,112KB) KV x3.
// ---------------------------------------------------------------------------
#define FA_KV_STAGE (2 * 128 * 64 * 2)          // K 16KB + V 16KB
#define FA_SMEM (16384 + 3 * FA_KV_STAGE)       // 112KB

__global__ void __launch_bounds__(256) flash_attn_kernel() {
    extern __shared__ __align__(16) char dyn[];
    bf16* Qs = (bf16*)dyn;

    const int tid  = threadIdx.x;
    const int lane = tid & 31;
    const int w    = tid >> 5;
    const int q0   = blockIdx.x * 128;
    const int bh   = blockIdx.y;
    const int b    = bh / HH, h = bh % HH;

    const int lrow8  = lane & 7;
    const int rowadd = ((lane >> 3) & 1) * 8;
    const int kadd   = ((lane >> 4) & 1) * 8;
    const int g = lane >> 2, t = lane & 3;

    // ---- load Q tile (128x64), build register A-fragments ----
#pragma unroll
    for (int i = 0; i < 4; ++i) {
        int lin = i * 256 + tid;
        int row = lin >> 3, ch = lin & 7;
        cp_async16(&Qs[sw64(row, ch * 8)],
                   gb_qkv + (size_t)(b * SS_ + q0 + row) * QKVD + h * DK + ch * 8);
    }
    cp_commit();
    cp_wait<0>();
    __syncthreads();

    unsigned aq[4][4];
#pragma unroll
    for (int kb = 0; kb < 4; ++kb)
        ldsm_x4(aq[kb], &Qs[sw64(w * 16 + lrow8 + rowadd, kb * 16 + kadd)]);
    __syncthreads();   // Q consumed; region reused for mask ring below

    auto load_kv = [&](int kt) {
        int s = kt % 3;
        bf16* Ks = (bf16*)(dyn + 16384 + s * FA_KV_STAGE);
        bf16* Vs = Ks + 128 * 64;
        unsigned* Ms = (unsigned*)(dyn + s * 2048);
        const int kv0 = kt * 128;
#pragma unroll
        for (int i = 0; i < 4; ++i) {
            int lin = i * 256 + tid;
            int row = lin >> 3, ch = lin & 7;
            size_t src = (size_t)(b * SS_ + kv0 + row) * QKVD + h * DK + ch * 8;
            cp_async16(&Ks[sw64(row, ch * 8)], gb_qkv + src + DD);
            cp_async16(&Vs[sw64(row, ch * 8)], gb_qkv + src + 2 * DD);
        }
        if (tid < 128)
            cp_async16(&Ms[tid * 4],
                       gb_maskbits + (size_t)(b * SS_ + q0 + tid) * 64 + kt * 4);
    };

    float oacc[8][4];
#pragma unroll
    for (int j = 0; j < 8; ++j)
#pragma unroll
        for (int e = 0; e < 4; ++e) oacc[j][e] = 0.f;
    float m0r = -3.0e38f, m1r = -3.0e38f, l0 = 0.f, l1 = 0.f;

    load_kv(0);
    cp_commit();

    for (int kt = 0; kt < 16; ++kt) {
        if (kt + 1 < 16) {
            load_kv(kt + 1);     // targets (kt+1)%3: laggards hold (kt+2)%3 -- disjoint
            cp_commit();
            cp_wait<1>();
        } else {
            cp_wait<0>();
        }
        __syncthreads();

        const int s = kt % 3;
        const bf16* Ks = (const bf16*)(dyn + 16384 + s * FA_KV_STAGE);
        const bf16* Vs = Ks + 128 * 64;
        const unsigned* Ms = (const unsigned*)(dyn + s * 2048);

        // ---- S = Q K^T ----
        float sacc[16][4];
#pragma unroll
        for (int j = 0; j < 16; ++j)
#pragma unroll
            for (int e = 0; e < 4; ++e) sacc[j][e] = 0.f;
#pragma unroll
        for (int kb = 0; kb < 4; ++kb) {
#pragma unroll
            for (int pr = 0; pr < 8; ++pr) {
                unsigned t4[4];
                ldsm_x4(t4, &Ks[sw64(pr * 16 + lrow8 + rowadd, kb * 16 + kadd)]);
                unsigned b0[2] = {t4[0], t4[2]}, b1[2] = {t4[1], t4[3]};
                mma_bf16(sacc[2 * pr],     aq[kb], b0);
                mma_bf16(sacc[2 * pr + 1], aq[kb], b1);
            }
        }

        // ---- mask + scale + row max ----
        const int r0 = w * 16 + g;
        float nm0 = -3.0e38f, nm1 = -3.0e38f;
#pragma unroll
        for (int j = 0; j < 16; ++j) {
            unsigned w0 = Ms[r0 * 4 + (j >> 2)];
            unsigned w1 = Ms[(r0 + 8) * 4 + (j >> 2)];
            int c = 8 * j + 2 * t;
            sacc[j][0] = ((w0 >> (c & 31)) & 1u)       ? sacc[j][0] * 0.125f : -1e9f;
            sacc[j][1] = ((w0 >> ((c + 1) & 31)) & 1u) ? sacc[j][1] * 0.125f : -1e9f;
            sacc[j][2] = ((w1 >> (c & 31)) & 1u)       ? sacc[j][2] * 0.125f : -1e9f;
            sacc[j][3] = ((w1 >> ((c + 1) & 31)) & 1u) ? sacc[j][3] * 0.125f : -1e9f;
            nm0 = fmaxf(nm0, fmaxf(sacc[j][0], sacc[j][1]));
            nm1 = fmaxf(nm1, fmaxf(sacc[j][2], sacc[j][3]));
        }
#pragma unroll
        for (int o = 1; o <= 2; o <<= 1) {
            nm0 = fmaxf(nm0, __shfl_xor_sync(0xffffffffu, nm0, o));
            nm1 = fmaxf(nm1, __shfl_xor_sync(0xffffffffu, nm1, o));
        }

        // ---- online softmax ----
        float mn0 = fmaxf(m0r, nm0), mn1 = fmaxf(m1r, nm1);
        float a0 = __expf(m0r - mn0), a1 = __expf(m1r - mn1);
        m0r = mn0; m1r = mn1;
        float rs0 = 0.f, rs1 = 0.f;
#pragma unroll
        for (int j = 0; j < 16; ++j) {
            sacc[j][0] = __expf(sacc[j][0] - mn0);
            sacc[j][1] = __expf(sacc[j][1] - mn0);
            sacc[j][2] = __expf(sacc[j][2] - mn1);
            sacc[j][3] = __expf(sacc[j][3] - mn1);
            rs0 += sacc[j][0] + sacc[j][1];
            rs1 += sacc[j][2] + sacc[j][3];
        }
#pragma unroll
        for (int o = 1; o <= 2; o <<= 1) {
            rs0 += __shfl_xor_sync(0xffffffffu, rs0, o);
            rs1 += __shfl_xor_sync(0xffffffffu, rs1, o);
        }
        l0 = a0 * l0 + rs0;
        l1 = a1 * l1 + rs1;
#pragma unroll
        for (int j = 0; j < 8; ++j) {
            oacc[j][0] *= a0; oacc[j][1] *= a0;
            oacc[j][2] *= a1; oacc[j][3] *= a1;
        }

        // ---- O += P V ----
#pragma unroll
        for (int kb = 0; kb < 8; ++kb) {
            unsigned ap[4];
            ap[0] = pack_bf16x2(sacc[2 * kb][0],     sacc[2 * kb][1]);
            ap[1] = pack_bf16x2(sacc[2 * kb][2],     sacc[2 * kb][3]);
            ap[2] = pack_bf16x2(sacc[2 * kb + 1][0], sacc[2 * kb + 1][1]);
            ap[3] = pack_bf16x2(sacc[2 * kb + 1][2], sacc[2 * kb + 1][3]);
#pragma unroll
            for (int pr = 0; pr < 4; ++pr) {
                unsigned t4[4];
                ldsm_x4_t(t4, &Vs[sw64(kb * 16 + lrow8 + rowadd, pr * 16 + kadd)]);
                unsigned b0[2] = {t4[0], t4[1]}, b1[2] = {t4[2], t4[3]};
                mma_bf16(oacc[2 * pr],     ap, b0);
                mma_bf16(oacc[2 * pr + 1], ap, b1);
            }
        }
    }

    // ---- normalize + write ----
    float inv0 = 1.f / l0, inv1 = 1.f / l1;
    const int qa = b * SS_ + q0 + w * 16 + g;
#pragma unroll
    for (int j = 0; j < 8; ++j) {
        int d0 = h * DK + j * 8 + 2 * t;
        gb_attn[(size_t)qa * DD + d0]           = __float2bfloat16(oacc[j][0] * inv0);
        gb_attn[(size_t)qa * DD + d0 + 1]       = __float2bfloat16(oacc[j][1] * inv0);
        gb_attn[(size_t)(qa + 8) * DD + d0]     = __float2bfloat16(oacc[j][2] * inv1);
        gb_attn[(size_t)(qa + 8) * DD + d0 + 1] = __float2bfloat16(oacc[j][3] * inv1);
    }
}

// ---------------------------------------------------------------------------
// Elementwise / support kernels
// ---------------------------------------------------------------------------
__global__ void cvt_weights_kernel(const float* __restrict__ wq, const float* __restrict__ wk,
                                   const float* __restrict__ wv, const float* __restrict__ wo,
                                   const float* __restrict__ w1, const float* __restrict__ w2,
                                   const float* __restrict__ w3) {
    const int N1 = DD * DD;
    const int N2 = FF * DD;
    const int TOT = 4 * N1 + 3 * N2;
    int idx = blockIdx.x * blockDim.x + threadIdx.x;
    if (idx >= TOT) return;
    if (idx < N1)            gb_wqkv[idx] = __float2bfloat16(wq[idx]);
    else if (idx < 2 * N1)   gb_wqkv[idx] = __float2bfloat16(wk[idx - N1]);
    else if (idx < 3 * N1)   gb_wqkv[idx] = __float2bfloat16(wv[idx - 2 * N1]);
    else if (idx < 4 * N1)   gb_wo[idx - 3 * N1] = __float2bfloat16(wo[idx - 3 * N1]);
    else if (idx < 4 * N1 + N2) {
        int i = idx - 4 * N1;  gb_w13[i] = __float2bfloat16(w1[i]);
    } else if (idx < 4 * N1 + 2 * N2) {
        int i = idx - 4 * N1 - N2;  gb_w13[N2 + i] = __float2bfloat16(w3[i]);
    } else {
        int i = idx - 4 * N1 - 2 * N2;  gb_w2[i] = __float2bfloat16(w2[i]);
    }
}

__device__ __forceinline__ void rmsnorm_row(const float* __restrict__ in,
                                            const float* __restrict__ g,
                                            bf16* __restrict__ out) {
    __shared__ float red[8];
    int tid = threadIdx.x, lane = tid & 31, warp = tid >> 5;
    float ss = 0.f;
#pragma unroll
    for (int c = 0; c < 3; ++c) {
        float a = in[c * 256 + tid];
        ss += a * a;
    }
#pragma unroll
    for (int o = 16; o; o >>= 1) ss += __shfl_xor_sync(0xffffffffu, ss, o);
    if (lane == 0) red[warp] = ss;
    __syncthreads();
    float tot = 0.f;
#pragma unroll
    for (int i = 0; i < 8; ++i) tot += red[i];
    float sc = rsqrtf(tot / (float)DD + 1e-5f);
#pragma unroll
    for (int c = 0; c < 3; ++c) {
        int j = c * 256 + tid;
        out[j] = __float2bfloat16(g[j] * in[j] * sc);
    }
}

__global__ void rmsnorm_x_kernel(const float* __restrict__ x, const float* __restrict__ g) {
    rmsnorm_row(x + (size_t)blockIdx.x * DD, g, gb_xn + (size_t)blockIdx.x * DD);
}
__global__ void rmsnorm_h_kernel(const float* __restrict__ g) {
    rmsnorm_row(gb_h + (size_t)blockIdx.x * DD, g, gb_hn + (size_t)blockIdx.x * DD);
}

__global__ void mask_pack_kernel(const int* __restrict__ mask) {
    int row = blockIdx.x;
    int tid = threadIdx.x, lane = tid & 31, warp = tid >> 5;
    const int* mrow = mask + (size_t)row * SS_;
#pragma unroll
    for (int c = 0; c < 8; ++c) {
        int j = c * 256 + tid;
        unsigned bal = __ballot_sync(0xffffffffu, mrow[j] != 0);
        if (lane == 0) gb_maskbits[(size_t)row * 64 + c * 8 + warp] = bal;
    }
}

__global__ void silu_gate_kernel() {
    int idx = blockIdx.x * blockDim.x + threadIdx.x;
    if (idx >= MTOT * FF) return;
    int m = idx / FF;
    int j = idx - m * FF;
    float u = __bfloat162float(gb_ug[(size_t)m * (2 * FF) + j]);
    float gt = __bfloat162float(gb_ug[(size_t)m * (2 * FF) + FF + j]);
    float s = u / (1.f + __expf(-u));
    gb_t[idx] = __float2bfloat16(s * gt);
}

// ---------------------------------------------------------------------------
// Launch
// ---------------------------------------------------------------------------
extern "C" void kernel_launch(void* const* d_in, const int* in_sizes, int n_in,
                              void* d_out, int out_size) {
    const float* x      = (const float*)d_in[0];
    const int*   mask   = (const int*)d_in[1];
    const float* wq     = (const float*)d_in[2];
    const float* wk     = (const float*)d_in[3];
    const float* wv     = (const float*)d_in[4];
    const float* wo     = (const float*)d_in[5];
    const float* w1     = (const float*)d_in[6];
    const float* w2     = (const float*)d_in[7];
    const float* w3     = (const float*)d_in[8];
    const float* gattn  = (const float*)d_in[9];
    const float* gffn   = (const float*)d_in[10];
    float* out          = (float*)d_out;

    static bool attr_done = false;
    if (!attr_done) {
        cudaFuncSetAttribute(gemm_qkv_kernel, cudaFuncAttributeMaxDynamicSharedMemorySize, G_SMEM);
        cudaFuncSetAttribute(gemm_wo_kernel,  cudaFuncAttributeMaxDynamicSharedMemorySize, G_SMEM);
        cudaFuncSetAttribute(gemm_w13_kernel, cudaFuncAttributeMaxDynamicSharedMemorySize, G_SMEM);
        cudaFuncSetAttribute(gemm_w2_kernel,  cudaFuncAttributeMaxDynamicSharedMemorySize, G_SMEM);
        cudaFuncSetAttribute(flash_attn_kernel, cudaFuncAttributeMaxDynamicSharedMemorySize, FA_SMEM);
        attr_done = true;
    }

    const int CVT_TOT = 4 * DD * DD + 3 * FF * DD;
    cvt_weights_kernel<<<(CVT_TOT + 255) / 256, 256>>>(wq, wk, wv, wo, w1, w2, w3);
    mask_pack_kernel<<<BB * SS_, 256>>>(mask);
    rmsnorm_x_kernel<<<MTOT, 256>>>(x, gattn);

    gemm_qkv_kernel<<<dim3(MTOT / 128, QKVD / 128), 256, G_SMEM>>>();
    flash_attn_kernel<<<dim3(SS_ / 128, BH), 256, FA_SMEM>>>();

    gemm_wo_kernel<<<dim3(MTOT / 128, DD / 128), 256, G_SMEM>>>(x);
    rmsnorm_h_kernel<<<MTOT, 256>>>(gffn);

    gemm_w13_kernel<<<dim3(MTOT / 128, (2 * FF) / 128), 256, G_SMEM>>>();
    silu_gate_kernel<<<(MTOT * FF + 255) / 256, 256>>>();
    gemm_w2_kernel<<<dim3(MTOT / 128, DD / 128), 256, G_SMEM>>>(out);
}

// round 5
// speedup vs baseline: 2.0727x; 1.2568x over previous
#include <cuda_runtime.h>
#include <cuda_bf16.h>
#include <math.h>
#include <stdint.h>

// ---------------------------------------------------------------------------
// Problem constants: B=2, S=2048, D=768, H=12, Dk=64, F=3072
// ---------------------------------------------------------------------------
#define BB   2
#define SS_  2048
#define DD   768
#define HH   12
#define DK   64
#define FF   3072
#define MTOT 4096              // B*S
#define BH   24                // B*H
#define QKVD 2304              // 3*D

typedef __nv_bfloat16 bf16;

// ---------------------------------------------------------------------------
// Device scratch (allocation-free; __device__ globals per harness rules)
// ---------------------------------------------------------------------------
__device__ bf16 gb_wqkv[QKVD * DD];
__device__ bf16 gb_wo[DD * DD];
__device__ bf16 gb_w13[2 * FF * DD];    // interleaved: row 2f = w1_f, 2f+1 = w3_f
__device__ bf16 gb_w2[DD * FF];
__device__ bf16 gb_xn[MTOT * DD];
__device__ bf16 gb_qkv[MTOT * QKVD];
__device__ bf16 gb_attn[MTOT * DD];
__device__ float gb_h[MTOT * DD];
__device__ bf16 gb_hn[MTOT * DD];
__device__ bf16 gb_t[MTOT * FF];
__device__ unsigned gb_maskbits[BB * SS_ * (SS_ / 32)];

// ---------------------------------------------------------------------------
// MMA / ldmatrix / cp.async helpers
// ---------------------------------------------------------------------------
__device__ __forceinline__ void ldsm_x4(unsigned* r, const void* p) {
    unsigned addr = (unsigned)__cvta_generic_to_shared(p);
    asm volatile("ldmatrix.sync.aligned.m8n8.x4.shared.b16 {%0,%1,%2,%3}, [%4];\n"
                 : "=r"(r[0]), "=r"(r[1]), "=r"(r[2]), "=r"(r[3]) : "r"(addr));
}
__device__ __forceinline__ void ldsm_x4_t(unsigned* r, const void* p) {
    unsigned addr = (unsigned)__cvta_generic_to_shared(p);
    asm volatile("ldmatrix.sync.aligned.m8n8.x4.trans.shared.b16 {%0,%1,%2,%3}, [%4];\n"
                 : "=r"(r[0]), "=r"(r[1]), "=r"(r[2]), "=r"(r[3]) : "r"(addr));
}
__device__ __forceinline__ void mma_bf16(float* c, const unsigned* a, const unsigned* b) {
    asm volatile(
        "mma.sync.aligned.m16n8k16.row.col.f32.bf16.bf16.f32 "
        "{%0,%1,%2,%3}, {%4,%5,%6,%7}, {%8,%9}, {%0,%1,%2,%3};\n"
        : "+f"(c[0]), "+f"(c[1]), "+f"(c[2]), "+f"(c[3])
        : "r"(a[0]), "r"(a[1]), "r"(a[2]), "r"(a[3]), "r"(b[0]), "r"(b[1]));
}
__device__ __forceinline__ void cp_async16(void* smem, const void* g) {
    unsigned addr = (unsigned)__cvta_generic_to_shared(smem);
    asm volatile("cp.async.cg.shared.global [%0], [%1], 16;\n" :: "r"(addr), "l"(g));
}
__device__ __forceinline__ void cp_commit() { asm volatile("cp.async.commit_group;\n"); }
template <int N>
__device__ __forceinline__ void cp_wait() { asm volatile("cp.async.wait_group %0;\n" :: "n"(N)); }

__device__ __forceinline__ unsigned pack_bf16x2(float lo, float hi) {
    __nv_bfloat162 h2 = __floats2bfloat162_rn(lo, hi);
    return *reinterpret_cast<unsigned*>(&h2);
}

// Swizzled index within a 128B-row tile (row-major, 64 halves per row).
__device__ __forceinline__ int sw64(int row, int k) {
    int chunk = k >> 3, within = k & 7;
    return row * 64 + (((chunk ^ (row & 7)) << 3) | within);
}

// ---------------------------------------------------------------------------
// Classic NT GEMM (mma.sync): C[m,n] = sum_k A[m,k]*B[n,k].
// BM=BN=128, BK=64. 256 threads = 8 warps (4 M x 2 N), warp tile 32x64.
// 2-stage cp.async ring (64KB) so 2 CTAs co-reside per SM.
//   iter kt: wait(load kt) -> barrier -> issue load kt+2? no: lookahead-1:
//   wait<0> -> barrier -> issue load kt+1 -> compute kt.
// Ring safety: load kt+1 writes stage (kt+1)%2 which compute kt-1 read;
// the barrier (all threads past wait) separates them.
// ---------------------------------------------------------------------------
#define G_BK 64
#define G_STAGE_BYTES (2 * 128 * G_BK * 2)   // A 16KB + B 16KB = 32KB
#define G_SMEM (2 * G_STAGE_BYTES)           // 64KB

template <typename Epi>
__device__ __forceinline__ void gemm_block(const bf16* __restrict__ A, int lda,
                                           const bf16* __restrict__ B, int ldb,
                                           int K, Epi epi) {
    extern __shared__ __align__(16) char dyn[];

    const int tid  = threadIdx.x;
    const int lane = tid & 31;
    const int warp = tid >> 5;
    const int wr   = warp >> 1;   // 0..3
    const int wc   = warp & 1;    // 0..1

    const int m0 = blockIdx.x * 128;
    const int n0 = blockIdx.y * 128;

    float acc[2][8][4];
#pragma unroll
    for (int i = 0; i < 2; ++i)
#pragma unroll
        for (int j = 0; j < 8; ++j)
#pragma unroll
            for (int e = 0; e < 4; ++e) acc[i][j][e] = 0.f;

    const int lrow8  = lane & 7;
    const int rowadd = ((lane >> 3) & 1) * 8;
    const int kadd   = ((lane >> 4) & 1) * 8;

    auto load_tile = [&](int kt, int s) {
        bf16* As = (bf16*)(dyn + s * G_STAGE_BYTES);
        bf16* Bs = As + 128 * 64;
#pragma unroll
        for (int i = 0; i < 4; ++i) {
            int lin = i * 256 + tid;
            int row = lin >> 3, ch = lin & 7;
            cp_async16(&As[sw64(row, ch * 8)],
                       A + (size_t)(m0 + row) * lda + kt * G_BK + ch * 8);
        }
#pragma unroll
        for (int i = 0; i < 4; ++i) {
            int lin = i * 256 + tid;
            int row = lin >> 3, ch = lin & 7;
            cp_async16(&Bs[sw64(row, ch * 8)],
                       B + (size_t)(n0 + row) * ldb + kt * G_BK + ch * 8);
        }
    };

    const int nt = K / G_BK;
    load_tile(0, 0);
    cp_commit();

    for (int kt = 0; kt < nt; ++kt) {
        cp_wait<0>();
        __syncthreads();
        if (kt + 1 < nt) {
            load_tile(kt + 1, (kt + 1) & 1);
            cp_commit();
        }

        const bf16* As = (const bf16*)(dyn + (kt & 1) * G_STAGE_BYTES);
        const bf16* Bs = As + 128 * 64;
#pragma unroll
        for (int ks = 0; ks < 4; ++ks) {
            unsigned af[2][4];
#pragma unroll
            for (int im = 0; im < 2; ++im)
                ldsm_x4(af[im], &As[sw64(wr * 32 + im * 16 + lrow8 + rowadd,
                                         ks * 16 + kadd)]);
            unsigned bfr[8][2];
#pragma unroll
            for (int p = 0; p < 4; ++p) {
                unsigned t4[4];
                ldsm_x4(t4, &Bs[sw64(wc * 64 + p * 16 + lrow8 + rowadd,
                                     ks * 16 + kadd)]);
                bfr[2 * p][0]     = t4[0]; bfr[2 * p][1]     = t4[2];
                bfr[2 * p + 1][0] = t4[1]; bfr[2 * p + 1][1] = t4[3];
            }
#pragma unroll
            for (int im = 0; im < 2; ++im)
#pragma unroll
                for (int in = 0; in < 8; ++in)
                    mma_bf16(acc[im][in], af[im], bfr[in]);
        }
    }

    // Pair epilogue: epi2(m, n_even, v0, v1)
    const int g = lane >> 2, t = lane & 3;
#pragma unroll
    for (int im = 0; im < 2; ++im) {
#pragma unroll
        for (int in = 0; in < 8; ++in) {
            int mb = m0 + wr * 32 + im * 16;
            int nb = n0 + wc * 64 + in * 8 + 2 * t;
            epi(mb + g,     nb, acc[im][in][0], acc[im][in][1]);
            epi(mb + g + 8, nb, acc[im][in][2], acc[im][in][3]);
        }
    }
}

// ---------------------------------------------------------------------------
// Epilogues (pair interface; n even)
// ---------------------------------------------------------------------------
struct EpiQKV {
    __device__ void operator()(int m, int n, float v0, float v1) const {
        *reinterpret_cast<unsigned*>(&gb_qkv[(size_t)m * QKVD + n]) = pack_bf16x2(v0, v1);
    }
};
struct EpiWO {
    const float* x;
    __device__ void operator()(int m, int n, float v0, float v1) const {
        size_t i = (size_t)m * DD + n;
        float2 xv = *reinterpret_cast<const float2*>(&x[i]);
        *reinterpret_cast<float2*>(&gb_h[i]) = make_float2(xv.x + v0, xv.y + v1);
    }
};
struct EpiW13 {   // interleaved: v0 = u_f (w1), v1 = g_f (w3), f = n/2
    __device__ void operator()(int m, int n, float v0, float v1) const {
        float s = v0 / (1.f + __expf(-v0));
        gb_t[(size_t)m * FF + (n >> 1)] = __float2bfloat16(s * v1);
    }
};
struct EpiW2 {
    float* out;
    __device__ void operator()(int m, int n, float v0, float v1) const {
        size_t i = (size_t)m * DD + n;
        float2 hv = *reinterpret_cast<const float2*>(&gb_h[i]);
        *reinterpret_cast<float2*>(&out[i]) = make_float2(hv.x + v0, hv.y + v1);
    }
};

__global__ void __launch_bounds__(256, 2) gemm_qkv_kernel() {
    gemm_block(gb_xn, DD, gb_wqkv, DD, DD, EpiQKV{});
}
__global__ void __launch_bounds__(256, 2) gemm_wo_kernel(const float* __restrict__ x) {
    gemm_block(gb_attn, DD, gb_wo, DD, DD, EpiWO{x});
}
__global__ void __launch_bounds__(256, 2) gemm_w13_kernel() {
    gemm_block(gb_hn, DD, gb_w13, DD, DD, EpiW13{});
}
__global__ void __launch_bounds__(256, 2) gemm_w2_kernel(float* __restrict__ out) {
    gemm_block(gb_t, FF, gb_w2, FF, FF, EpiW2{out});
}

// ---------------------------------------------------------------------------
// Flash attention with 3-stage K/V/mask prefetch ring (unchanged, 112KB)
// ---------------------------------------------------------------------------
#define FA_KV_STAGE (2 * 128 * 64 * 2)          // K 16KB + V 16KB
#define FA_SMEM (16384 + 3 * FA_KV_STAGE)       // 112KB

__global__ void __launch_bounds__(256) flash_attn_kernel() {
    extern __shared__ __align__(16) char dyn[];
    bf16* Qs = (bf16*)dyn;

    const int tid  = threadIdx.x;
    const int lane = tid & 31;
    const int w    = tid >> 5;
    const int q0   = blockIdx.x * 128;
    const int bh   = blockIdx.y;
    const int b    = bh / HH, h = bh % HH;

    const int lrow8  = lane & 7;
    const int rowadd = ((lane >> 3) & 1) * 8;
    const int kadd   = ((lane >> 4) & 1) * 8;
    const int g = lane >> 2, t = lane & 3;

#pragma unroll
    for (int i = 0; i < 4; ++i) {
        int lin = i * 256 + tid;
        int row = lin >> 3, ch = lin & 7;
        cp_async16(&Qs[sw64(row, ch * 8)],
                   gb_qkv + (size_t)(b * SS_ + q0 + row) * QKVD + h * DK + ch * 8);
    }
    cp_commit();
    cp_wait<0>();
    __syncthreads();

    unsigned aq[4][4];
#pragma unroll
    for (int kb = 0; kb < 4; ++kb)
        ldsm_x4(aq[kb], &Qs[sw64(w * 16 + lrow8 + rowadd, kb * 16 + kadd)]);
    __syncthreads();

    auto load_kv = [&](int kt) {
        int s = kt % 3;
        bf16* Ks = (bf16*)(dyn + 16384 + s * FA_KV_STAGE);
        bf16* Vs = Ks + 128 * 64;
        unsigned* Ms = (unsigned*)(dyn + s * 2048);
        const int kv0 = kt * 128;
#pragma unroll
        for (int i = 0; i < 4; ++i) {
            int lin = i * 256 + tid;
            int row = lin >> 3, ch = lin & 7;
            size_t src = (size_t)(b * SS_ + kv0 + row) * QKVD + h * DK + ch * 8;
            cp_async16(&Ks[sw64(row, ch * 8)], gb_qkv + src + DD);
            cp_async16(&Vs[sw64(row, ch * 8)], gb_qkv + src + 2 * DD);
        }
        if (tid < 128)
            cp_async16(&Ms[tid * 4],
                       gb_maskbits + (size_t)(b * SS_ + q0 + tid) * 64 + kt * 4);
    };

    float oacc[8][4];
#pragma unroll
    for (int j = 0; j < 8; ++j)
#pragma unroll
        for (int e = 0; e < 4; ++e) oacc[j][e] = 0.f;
    float m0r = -3.0e38f, m1r = -3.0e38f, l0 = 0.f, l1 = 0.f;

    load_kv(0);
    cp_commit();

    for (int kt = 0; kt < 16; ++kt) {
        if (kt + 1 < 16) {
            load_kv(kt + 1);
            cp_commit();
            cp_wait<1>();
        } else {
            cp_wait<0>();
        }
        __syncthreads();

        const int s = kt % 3;
        const bf16* Ks = (const bf16*)(dyn + 16384 + s * FA_KV_STAGE);
        const bf16* Vs = Ks + 128 * 64;
        const unsigned* Ms = (const unsigned*)(dyn + s * 2048);

        float sacc[16][4];
#pragma unroll
        for (int j = 0; j < 16; ++j)
#pragma unroll
            for (int e = 0; e < 4; ++e) sacc[j][e] = 0.f;
#pragma unroll
        for (int kb = 0; kb < 4; ++kb) {
#pragma unroll
            for (int pr = 0; pr < 8; ++pr) {
                unsigned t4[4];
                ldsm_x4(t4, &Ks[sw64(pr * 16 + lrow8 + rowadd, kb * 16 + kadd)]);
                unsigned b0[2] = {t4[0], t4[2]}, b1[2] = {t4[1], t4[3]};
                mma_bf16(sacc[2 * pr],     aq[kb], b0);
                mma_bf16(sacc[2 * pr + 1], aq[kb], b1);
            }
        }

        const int r0 = w * 16 + g;
        float nm0 = -3.0e38f, nm1 = -3.0e38f;
#pragma unroll
        for (int j = 0; j < 16; ++j) {
            unsigned w0 = Ms[r0 * 4 + (j >> 2)];
            unsigned w1 = Ms[(r0 + 8) * 4 + (j >> 2)];
            int c = 8 * j + 2 * t;
            sacc[j][0] = ((w0 >> (c & 31)) & 1u)       ? sacc[j][0] * 0.125f : -1e9f;
            sacc[j][1] = ((w0 >> ((c + 1) & 31)) & 1u) ? sacc[j][1] * 0.125f : -1e9f;
            sacc[j][2] = ((w1 >> (c & 31)) & 1u)       ? sacc[j][2] * 0.125f : -1e9f;
            sacc[j][3] = ((w1 >> ((c + 1) & 31)) & 1u) ? sacc[j][3] * 0.125f : -1e9f;
            nm0 = fmaxf(nm0, fmaxf(sacc[j][0], sacc[j][1]));
            nm1 = fmaxf(nm1, fmaxf(sacc[j][2], sacc[j][3]));
        }
#pragma unroll
        for (int o = 1; o <= 2; o <<= 1) {
            nm0 = fmaxf(nm0, __shfl_xor_sync(0xffffffffu, nm0, o));
            nm1 = fmaxf(nm1, __shfl_xor_sync(0xffffffffu, nm1, o));
        }

        float mn0 = fmaxf(m0r, nm0), mn1 = fmaxf(m1r, nm1);
        float a0 = __expf(m0r - mn0), a1 = __expf(m1r - mn1);
        m0r = mn0; m1r = mn1;
        float rs0 = 0.f, rs1 = 0.f;
#pragma unroll
        for (int j = 0; j < 16; ++j) {
            sacc[j][0] = __expf(sacc[j][0] - mn0);
            sacc[j][1] = __expf(sacc[j][1] - mn0);
            sacc[j][2] = __expf(sacc[j][2] - mn1);
            sacc[j][3] = __expf(sacc[j][3] - mn1);
            rs0 += sacc[j][0] + sacc[j][1];
            rs1 += sacc[j][2] + sacc[j][3];
        }
#pragma unroll
        for (int o = 1; o <= 2; o <<= 1) {
            rs0 += __shfl_xor_sync(0xffffffffu, rs0, o);
            rs1 += __shfl_xor_sync(0xffffffffu, rs1, o);
        }
        l0 = a0 * l0 + rs0;
        l1 = a1 * l1 + rs1;
#pragma unroll
        for (int j = 0; j < 8; ++j) {
            oacc[j][0] *= a0; oacc[j][1] *= a0;
            oacc[j][2] *= a1; oacc[j][3] *= a1;
        }

#pragma unroll
        for (int kb = 0; kb < 8; ++kb) {
            unsigned ap[4];
            ap[0] = pack_bf16x2(sacc[2 * kb][0],     sacc[2 * kb][1]);
            ap[1] = pack_bf16x2(sacc[2 * kb][2],     sacc[2 * kb][3]);
            ap[2] = pack_bf16x2(sacc[2 * kb + 1][0], sacc[2 * kb + 1][1]);
            ap[3] = pack_bf16x2(sacc[2 * kb + 1][2], sacc[2 * kb + 1][3]);
#pragma unroll
            for (int pr = 0; pr < 4; ++pr) {
                unsigned t4[4];
                ldsm_x4_t(t4, &Vs[sw64(kb * 16 + lrow8 + rowadd, pr * 16 + kadd)]);
                unsigned b0[2] = {t4[0], t4[1]}, b1[2] = {t4[2], t4[3]};
                mma_bf16(oacc[2 * pr],     ap, b0);
                mma_bf16(oacc[2 * pr + 1], ap, b1);
            }
        }
    }

    float inv0 = 1.f / l0, inv1 = 1.f / l1;
    const int qa = b * SS_ + q0 + w * 16 + g;
#pragma unroll
    for (int j = 0; j < 8; ++j) {
        int d0 = h * DK + j * 8 + 2 * t;
        *reinterpret_cast<unsigned*>(&gb_attn[(size_t)qa * DD + d0]) =
            pack_bf16x2(oacc[j][0] * inv0, oacc[j][1] * inv0);
        *reinterpret_cast<unsigned*>(&gb_attn[(size_t)(qa + 8) * DD + d0]) =
            pack_bf16x2(oacc[j][2] * inv1, oacc[j][3] * inv1);
    }
}

// ---------------------------------------------------------------------------
// Elementwise / support kernels
// ---------------------------------------------------------------------------
__global__ void cvt_weights_kernel(const float* __restrict__ wq, const float* __restrict__ wk,
                                   const float* __restrict__ wv, const float* __restrict__ wo,
                                   const float* __restrict__ w1, const float* __restrict__ w2,
                                   const float* __restrict__ w3) {
    const int N1 = DD * DD;
    const int N2 = FF * DD;
    const int TOT = 4 * N1 + 3 * N2;
    int idx = blockIdx.x * blockDim.x + threadIdx.x;
    if (idx >= TOT) return;
    if (idx < N1)            gb_wqkv[idx] = __float2bfloat16(wq[idx]);
    else if (idx < 2 * N1)   gb_wqkv[idx] = __float2bfloat16(wk[idx - N1]);
    else if (idx < 3 * N1)   gb_wqkv[idx] = __float2bfloat16(wv[idx - 2 * N1]);
    else if (idx < 4 * N1)   gb_wo[idx - 3 * N1] = __float2bfloat16(wo[idx - 3 * N1]);
    else if (idx < 4 * N1 + N2) {
        int i = idx - 4 * N1;            // w1 row f -> interleaved row 2f
        int f = i / DD, d = i - f * DD;
        gb_w13[(size_t)(2 * f) * DD + d] = __float2bfloat16(w1[i]);
    } else if (idx < 4 * N1 + 2 * N2) {
        int i = idx - 4 * N1 - N2;       // w3 row f -> interleaved row 2f+1
        int f = i / DD, d = i - f * DD;
        gb_w13[(size_t)(2 * f + 1) * DD + d] = __float2bfloat16(w3[i]);
    } else {
        int i = idx - 4 * N1 - 2 * N2;
        gb_w2[i] = __float2bfloat16(w2[i]);
    }
}

__device__ __forceinline__ void rmsnorm_row(const float* __restrict__ in,
                                            const float* __restrict__ g,
                                            bf16* __restrict__ out) {
    __shared__ float red[8];
    int tid = threadIdx.x, lane = tid & 31, warp = tid >> 5;
    float ss = 0.f;
#pragma unroll
    for (int c = 0; c < 3; ++c) {
        float a = in[c * 256 + tid];
        ss += a * a;
    }
#pragma unroll
    for (int o = 16; o; o >>= 1) ss += __shfl_xor_sync(0xffffffffu, ss, o);
    if (lane == 0) red[warp] = ss;
    __syncthreads();
    float tot = 0.f;
#pragma unroll
    for (int i = 0; i < 8; ++i) tot += red[i];
    float sc = rsqrtf(tot / (float)DD + 1e-5f);
#pragma unroll
    for (int c = 0; c < 3; ++c) {
        int j = c * 256 + tid;
        out[j] = __float2bfloat16(g[j] * in[j] * sc);
    }
}

__global__ void rmsnorm_x_kernel(const float* __restrict__ x, const float* __restrict__ g) {
    rmsnorm_row(x + (size_t)blockIdx.x * DD, g, gb_xn + (size_t)blockIdx.x * DD);
}
__global__ void rmsnorm_h_kernel(const float* __restrict__ g) {
    rmsnorm_row(gb_h + (size_t)blockIdx.x * DD, g, gb_hn + (size_t)blockIdx.x * DD);
}

__global__ void mask_pack_kernel(const int* __restrict__ mask) {
    int row = blockIdx.x;
    int tid = threadIdx.x, lane = tid & 31, warp = tid >> 5;
    const int* mrow = mask + (size_t)row * SS_;
#pragma unroll
    for (int c = 0; c < 8; ++c) {
        int j = c * 256 + tid;
        unsigned bal = __ballot_sync(0xffffffffu, mrow[j] != 0);
        if (lane == 0) gb_maskbits[(size_t)row * 64 + c * 8 + warp] = bal;
    }
}

// ---------------------------------------------------------------------------
// Launch
// ---------------------------------------------------------------------------
extern "C" void kernel_launch(void* const* d_in, const int* in_sizes, int n_in,
                              void* d_out, int out_size) {
    const float* x      = (const float*)d_in[0];
    const int*   mask   = (const int*)d_in[1];
    const float* wq     = (const float*)d_in[2];
    const float* wk     = (const float*)d_in[3];
    const float* wv     = (const float*)d_in[4];
    const float* wo     = (const float*)d_in[5];
    const float* w1     = (const float*)d_in[6];
    const float* w2     = (const float*)d_in[7];
    const float* w3     = (const float*)d_in[8];
    const float* gattn  = (const float*)d_in[9];
    const float* gffn   = (const float*)d_in[10];
    float* out          = (float*)d_out;

    static bool attr_done = false;
    if (!attr_done) {
        cudaFuncSetAttribute(gemm_qkv_kernel, cudaFuncAttributeMaxDynamicSharedMemorySize, G_SMEM);
        cudaFuncSetAttribute(gemm_wo_kernel,  cudaFuncAttributeMaxDynamicSharedMemorySize, G_SMEM);
        cudaFuncSetAttribute(gemm_w13_kernel, cudaFuncAttributeMaxDynamicSharedMemorySize, G_SMEM);
        cudaFuncSetAttribute(gemm_w2_kernel,  cudaFuncAttributeMaxDynamicSharedMemorySize, G_SMEM);
        cudaFuncSetAttribute(flash_attn_kernel, cudaFuncAttributeMaxDynamicSharedMemorySize, FA_SMEM);
        attr_done = true;
    }

    const int CVT_TOT = 4 * DD * DD + 3 * FF * DD;
    cvt_weights_kernel<<<(CVT_TOT + 255) / 256, 256>>>(wq, wk, wv, wo, w1, w2, w3);
    mask_pack_kernel<<<BB * SS_, 256>>>(mask);
    rmsnorm_x_kernel<<<MTOT, 256>>>(x, gattn);

    gemm_qkv_kernel<<<dim3(MTOT / 128, QKVD / 128), 256, G_SMEM>>>();
    flash_attn_kernel<<<dim3(SS_ / 128, BH), 256, FA_SMEM>>>();

    gemm_wo_kernel<<<dim3(MTOT / 128, DD / 128), 256, G_SMEM>>>(x);
    rmsnorm_h_kernel<<<MTOT, 256>>>(gffn);

    gemm_w13_kernel<<<dim3(MTOT / 128, (2 * FF) / 128), 256, G_SMEM>>>();
    gemm_w2_kernel<<<dim3(MTOT / 128, DD / 128), 256, G_SMEM>>>(out);
}